// round 2
// baseline (speedup 1.0000x reference)
#include <cuda_runtime.h>
#include <math.h>

#define S_    1024
#define H_    2048
#define NH_   16
#define DH_   128
#define ROT_  32
#define NN_   32
#define MK_   8192
#define HQKV_ 6144

// ---------------- scratch (device globals; no allocation) ----------------
__device__ __align__(16) float g_qkv[S_ * HQKV_];     // [s][6144]
__device__ __align__(16) float g_q  [NH_ * S_ * DH_]; // [h][s][128]
__device__ __align__(16) float g_k  [NH_ * S_ * DH_];
__device__ __align__(16) float g_v  [NH_ * S_ * DH_];
__device__ __align__(16) float g_ctx[S_ * H_];        // [s][h*128+d]
__device__ __align__(16) float g_topv[NH_ * S_ * NN_];
__device__ __align__(16) int   g_topi[NH_ * S_ * NN_];

// ---------------- generic NT SGEMM: C[M,N] = A[M,K] * B[N,K]^T + bias ----
// BM=BN=128, BK=8, 256 threads, 8x8 micro-tile. M,N multiples of 128, K of 8.
__device__ __forceinline__ void sgemm_nt_body(
    const float* __restrict__ A, const float* __restrict__ B,
    const float* __restrict__ bias, float* __restrict__ C,
    int N, int K)
{
    __shared__ float As[8 * 128];
    __shared__ float Bs[8 * 128];
    const int tid  = threadIdx.x;
    const int m0   = blockIdx.y * 128;
    const int n0   = blockIdx.x * 128;
    const int ty   = tid >> 4, tx = tid & 15;
    const int lrow = tid >> 1, lk4 = (tid & 1) * 4;

    float c[8][8];
#pragma unroll
    for (int i = 0; i < 8; i++)
#pragma unroll
        for (int j = 0; j < 8; j++) c[i][j] = 0.f;

    const float* Ab = A + (size_t)(m0 + lrow) * K + lk4;
    const float* Bb = B + (size_t)(n0 + lrow) * K + lk4;

    for (int k0 = 0; k0 < K; k0 += 8) {
        float4 av = *(const float4*)(Ab + k0);
        float4 bv = *(const float4*)(Bb + k0);
        As[(lk4 + 0) * 128 + lrow] = av.x;
        As[(lk4 + 1) * 128 + lrow] = av.y;
        As[(lk4 + 2) * 128 + lrow] = av.z;
        As[(lk4 + 3) * 128 + lrow] = av.w;
        Bs[(lk4 + 0) * 128 + lrow] = bv.x;
        Bs[(lk4 + 1) * 128 + lrow] = bv.y;
        Bs[(lk4 + 2) * 128 + lrow] = bv.z;
        Bs[(lk4 + 3) * 128 + lrow] = bv.w;
        __syncthreads();
#pragma unroll
        for (int kk = 0; kk < 8; kk++) {
            float a[8], b[8];
            *(float4*)&a[0] = *(const float4*)&As[kk * 128 + ty * 8];
            *(float4*)&a[4] = *(const float4*)&As[kk * 128 + ty * 8 + 4];
            *(float4*)&b[0] = *(const float4*)&Bs[kk * 128 + tx * 8];
            *(float4*)&b[4] = *(const float4*)&Bs[kk * 128 + tx * 8 + 4];
#pragma unroll
            for (int i = 0; i < 8; i++)
#pragma unroll
                for (int j = 0; j < 8; j++) c[i][j] += a[i] * b[j];
        }
        __syncthreads();
    }
#pragma unroll
    for (int i = 0; i < 8; i++) {
        int row = m0 + ty * 8 + i;
#pragma unroll
        for (int j = 0; j < 8; j++) {
            int col = n0 + tx * 8 + j;
            C[(size_t)row * N + col] = c[i][j] + bias[col];
        }
    }
}

__global__ void qkv_gemm_kernel(const float* __restrict__ A,
                                const float* __restrict__ B,
                                const float* __restrict__ bias)
{
    sgemm_nt_body(A, B, bias, g_qkv, HQKV_, H_);
}

__global__ void out_gemm_kernel(const float* __restrict__ B,
                                const float* __restrict__ bias,
                                float* __restrict__ C)
{
    sgemm_nt_body(g_ctx, B, bias, C, H_, H_);
}

// ---------------- norm + rope + transpose into [h][s][d] -----------------
__global__ void norm_rope_kernel(const int* __restrict__ pos)
{
    const int s = blockIdx.x, h = blockIdx.y, d = threadIdx.x;
    const float* base = g_qkv + (size_t)s * HQKV_ + h * (3 * DH_);
    float qv = base[d], kv = base[DH_ + d], vv = base[2 * DH_ + d];

    float sq = qv * qv, sk = kv * kv;
#pragma unroll
    for (int o = 16; o > 0; o >>= 1) {
        sq += __shfl_xor_sync(0xffffffffu, sq, o);
        sk += __shfl_xor_sync(0xffffffffu, sk, o);
    }
    __shared__ float rq[4], rk[4];
    if ((d & 31) == 0) { rq[d >> 5] = sq; rk[d >> 5] = sk; }
    __syncthreads();
    float nq = sqrtf(rq[0] + rq[1] + rq[2] + rq[3]);
    float nk = sqrtf(rk[0] + rk[1] + rk[2] + rk[3]);
    float qn = qv / fmaxf(nq, 1e-12f);
    float kn = kv / fmaxf(nk, 1e-12f);

    __shared__ float qs[DH_], ks[DH_];
    qs[d] = qn; ks[d] = kn;
    __syncthreads();

    float qo = qn, ko = kn;
    if (d < ROT_) {
        int i = (d < 16) ? d : d - 16;
        float freq = powf(10000.0f, -(float)i / 16.0f);
        float ang  = (float)pos[s] * freq;   // position_ids: int32 (JAX x64 off)
        float cs = cosf(ang), sn = sinf(ang);
        float rqh = (d < 16) ? -qs[d + 16] : qs[d - 16];
        float rkh = (d < 16) ? -ks[d + 16] : ks[d - 16];
        qo = qn * cs + rqh * sn;
        ko = kn * cs + rkh * sn;
    }
    size_t o = ((size_t)h * S_ + s) * DH_ + d;
    g_q[o] = qo; g_k[o] = ko; g_v[o] = vv;
}

// ---------------- kNN scores + fused online top-32 -----------------------
// block = (q-tile of 128, head h); 256 threads; 64 key chunks of 128.
// smem: As 8*128, Bs 8*128, Sc 128*129, Tv 128*33, Ti 128*33
#define K3_SMEM ((1024 + 1024 + 128 * 129 + 128 * 33 + 128 * 33) * 4)

__global__ void knn_kernel(const float* __restrict__ mem_keys)
{
    extern __shared__ float sm[];
    float* As = sm;
    float* Bs = As + 1024;
    float* Sc = Bs + 1024;            // [128][129]
    float* Tv = Sc + 128 * 129;       // [128][33]
    int*   Ti = (int*)(Tv + 128 * 33);// [128][33]

    const int tid  = threadIdx.x;
    const int h    = blockIdx.y;
    const int q0   = blockIdx.x * 128;
    const int ty   = tid >> 4, tx = tid & 15;
    const int lrow = tid >> 1, lk4 = (tid & 1) * 4;

    float minv = -3.0e38f;
    int   minpos = 0;
    if (tid < 128) {
#pragma unroll
        for (int n = 0; n < NN_; n++) { Tv[tid * 33 + n] = -3.0e38f; Ti[tid * 33 + n] = 0; }
    }

    const float* Ab = g_q + ((size_t)h * S_ + q0 + lrow) * DH_ + lk4;

    for (int nc = 0; nc < MK_ / 128; nc++) {
        const int n0 = nc * 128;
        const float* Bb = mem_keys + ((size_t)h * MK_ + n0 + lrow) * DH_ + lk4;

        float c[8][8];
#pragma unroll
        for (int i = 0; i < 8; i++)
#pragma unroll
            for (int j = 0; j < 8; j++) c[i][j] = 0.f;

        for (int k0 = 0; k0 < DH_; k0 += 8) {
            float4 av = *(const float4*)(Ab + k0);
            float4 bv = *(const float4*)(Bb + k0);
            As[(lk4 + 0) * 128 + lrow] = av.x;
            As[(lk4 + 1) * 128 + lrow] = av.y;
            As[(lk4 + 2) * 128 + lrow] = av.z;
            As[(lk4 + 3) * 128 + lrow] = av.w;
            Bs[(lk4 + 0) * 128 + lrow] = bv.x;
            Bs[(lk4 + 1) * 128 + lrow] = bv.y;
            Bs[(lk4 + 2) * 128 + lrow] = bv.z;
            Bs[(lk4 + 3) * 128 + lrow] = bv.w;
            __syncthreads();
#pragma unroll
            for (int kk = 0; kk < 8; kk++) {
                float a[8], b[8];
                *(float4*)&a[0] = *(const float4*)&As[kk * 128 + ty * 8];
                *(float4*)&a[4] = *(const float4*)&As[kk * 128 + ty * 8 + 4];
                *(float4*)&b[0] = *(const float4*)&Bs[kk * 128 + tx * 8];
                *(float4*)&b[4] = *(const float4*)&Bs[kk * 128 + tx * 8 + 4];
#pragma unroll
                for (int i = 0; i < 8; i++)
#pragma unroll
                    for (int j = 0; j < 8; j++) c[i][j] += a[i] * b[j];
            }
            __syncthreads();
        }
#pragma unroll
        for (int i = 0; i < 8; i++)
#pragma unroll
            for (int j = 0; j < 8; j++)
                Sc[(ty * 8 + i) * 129 + tx * 8 + j] = c[i][j];
        __syncthreads();

        if (tid < 128) {
            const float* srow = Sc + tid * 129;
            float* tv = Tv + tid * 33;
            int*   ti = Ti + tid * 33;
            for (int n = 0; n < 128; n++) {
                float s = srow[n];
                if (s > minv) {
                    tv[minpos] = s; ti[minpos] = n0 + n;
                    minv = tv[0]; minpos = 0;
#pragma unroll
                    for (int t = 1; t < NN_; t++) {
                        float x = tv[t];
                        if (x < minv) { minv = x; minpos = t; }
                    }
                }
            }
        }
        __syncthreads();
    }
    if (tid < 128) {
#pragma unroll
        for (int n = 0; n < NN_; n++) {
            g_topv[((size_t)h * S_ + q0 + tid) * NN_ + n] = Tv[tid * 33 + n];
            g_topi[((size_t)h * S_ + q0 + tid) * NN_ + n] = Ti[tid * 33 + n];
        }
    }
}

// ---------------- flash attention (mem top-k init + causal local) --------
// block = (q-tile of 64, head); 256 threads.
// smem: Qs 128*68 (q^T), KV 128*68 (k^T, reused as V[64][132]),
//       Sc 64*65, m/l/corr 3*64, Ti 64*32 (ints)
#define K4_SMEM ((128 * 68 + 128 * 68 + 64 * 65 + 192 + 64 * 32) * 4)

__global__ void attn_kernel(const float* __restrict__ am,
                            const float* __restrict__ scale_param,
                            const float* __restrict__ mem_values)
{
    extern __shared__ float sm[];
    float* Qs  = sm;                  // [128][68] transposed q
    float* KV  = Qs + 128 * 68;       // k^T [128][68] or V [64][132]
    float* Sc  = KV + 128 * 68;       // [64][65]
    float* msh = Sc + 64 * 65;
    float* lsh = msh + 64;
    float* csh = lsh + 64;
    int*   Ti  = (int*)(csh + 64);    // [64][32]

    const int tid = threadIdx.x;
    const int h   = blockIdx.y;
    const int q0  = blockIdx.x * 64;
    const int ty  = tid >> 4, tx = tid & 15;
    const float scale = expf(scale_param[h]);

    // load Q tile transposed
    for (int idx = tid; idx < 64 * 32; idx += 256) {
        int row = idx >> 5, seg = idx & 31;
        float4 v = *(const float4*)(g_q + ((size_t)h * S_ + q0 + row) * DH_ + seg * 4);
        Qs[(seg * 4 + 0) * 68 + row] = v.x;
        Qs[(seg * 4 + 1) * 68 + row] = v.y;
        Qs[(seg * 4 + 2) * 68 + row] = v.z;
        Qs[(seg * 4 + 3) * 68 + row] = v.w;
    }
    // load top-k scores (scaled) + indices
    for (int idx = tid; idx < 64 * 32; idx += 256) {
        int q = idx >> 5, n = idx & 31;
        Sc[q * 65 + n] = g_topv[((size_t)h * S_ + q0 + q) * NN_ + n] * scale;
        Ti[q * 32 + n] = g_topi[((size_t)h * S_ + q0 + q) * NN_ + n];
    }
    __syncthreads();

    // mem softmax init
    if (tid < 64) {
        int q = tid;
        float mm = -3.0e38f;
        for (int n = 0; n < NN_; n++) mm = fmaxf(mm, Sc[q * 65 + n]);
        float ll = 0.f;
        for (int n = 0; n < NN_; n++) {
            float p = expf(Sc[q * 65 + n] - mm);
            Sc[q * 65 + n] = p;
            ll += p;
        }
        msh[q] = mm; lsh[q] = ll;
    }
    __syncthreads();

    float oacc[4][8];
#pragma unroll
    for (int i = 0; i < 4; i++)
#pragma unroll
        for (int j = 0; j < 8; j++) oacc[i][j] = 0.f;

    // mem PV: gather mem_values rows
#pragma unroll
    for (int i = 0; i < 4; i++) {
        int qr = ty * 4 + i;
        for (int n = 0; n < NN_; n++) {
            float w = Sc[qr * 65 + n];
            const float4* vr = (const float4*)(mem_values +
                ((size_t)h * MK_ + Ti[qr * 32 + n]) * DH_ + tx * 8);
            float4 v0 = vr[0], v1 = vr[1];
            oacc[i][0] += w * v0.x; oacc[i][1] += w * v0.y;
            oacc[i][2] += w * v0.z; oacc[i][3] += w * v0.w;
            oacc[i][4] += w * v1.x; oacc[i][5] += w * v1.y;
            oacc[i][6] += w * v1.z; oacc[i][7] += w * v1.w;
        }
    }

    const int kcmax = q0 / 64;
    for (int kc = 0; kc <= kcmax; kc++) {
        __syncthreads();  // previous chunk's PV / mem-PV done before KV reuse
        // load K tile transposed
        for (int idx = tid; idx < 64 * 32; idx += 256) {
            int row = idx >> 5, seg = idx & 31;
            float4 v = *(const float4*)(g_k + ((size_t)h * S_ + kc * 64 + row) * DH_ + seg * 4);
            KV[(seg * 4 + 0) * 68 + row] = v.x;
            KV[(seg * 4 + 1) * 68 + row] = v.y;
            KV[(seg * 4 + 2) * 68 + row] = v.z;
            KV[(seg * 4 + 3) * 68 + row] = v.w;
        }
        __syncthreads();

        float sc4[4][4];
#pragma unroll
        for (int i = 0; i < 4; i++)
#pragma unroll
            for (int j = 0; j < 4; j++) sc4[i][j] = 0.f;

#pragma unroll 8
        for (int kd = 0; kd < DH_; kd++) {
            float4 aq = *(const float4*)&Qs[kd * 68 + ty * 4];
            float4 bk = *(const float4*)&KV[kd * 68 + tx * 4];
            float a[4] = {aq.x, aq.y, aq.z, aq.w};
            float b[4] = {bk.x, bk.y, bk.z, bk.w};
#pragma unroll
            for (int i = 0; i < 4; i++)
#pragma unroll
                for (int j = 0; j < 4; j++) sc4[i][j] += a[i] * b[j];
        }
        // mask + scale + attention_mask
#pragma unroll
        for (int i = 0; i < 4; i++) {
            int qg = q0 + ty * 4 + i;
#pragma unroll
            for (int j = 0; j < 4; j++) {
                int kg = kc * 64 + tx * 4 + j;
                float v = (kg <= qg) ? (sc4[i][j] * scale + am[kg]) : -1.0e30f;
                Sc[(ty * 4 + i) * 65 + tx * 4 + j] = v;
            }
        }
        __syncthreads();

        if (tid < 64) {
            int q = tid;
            float mm = msh[q];
            float rmax = mm;
            for (int n = 0; n < 64; n++) rmax = fmaxf(rmax, Sc[q * 65 + n]);
            float cor = expf(mm - rmax);
            float ll = lsh[q] * cor;
            for (int n = 0; n < 64; n++) {
                float p = expf(Sc[q * 65 + n] - rmax);
                Sc[q * 65 + n] = p;
                ll += p;
            }
            msh[q] = rmax; lsh[q] = ll; csh[q] = cor;
        }
        __syncthreads();

        // load V tile (natural layout) over the KV buffer
        for (int idx = tid; idx < 64 * 32; idx += 256) {
            int row = idx >> 5, seg = idx & 31;
            float4 v = *(const float4*)(g_v + ((size_t)h * S_ + kc * 64 + row) * DH_ + seg * 4);
            *(float4*)&KV[row * 132 + seg * 4] = v;
        }
        __syncthreads();

        // PV accumulate with rescale
#pragma unroll
        for (int i = 0; i < 4; i++) {
            int qr = ty * 4 + i;
            float cor = csh[qr];
#pragma unroll
            for (int j = 0; j < 8; j++) oacc[i][j] *= cor;
            for (int n = 0; n < 64; n++) {
                float w = Sc[qr * 65 + n];
                float4 v0 = *(const float4*)&KV[n * 132 + tx * 8];
                float4 v1 = *(const float4*)&KV[n * 132 + tx * 8 + 4];
                oacc[i][0] += w * v0.x; oacc[i][1] += w * v0.y;
                oacc[i][2] += w * v0.z; oacc[i][3] += w * v0.w;
                oacc[i][4] += w * v1.x; oacc[i][5] += w * v1.y;
                oacc[i][6] += w * v1.z; oacc[i][7] += w * v1.w;
            }
        }
    }

    // write ctx transposed to [s][h*128+d]
#pragma unroll
    for (int i = 0; i < 4; i++) {
        int qr = ty * 4 + i;
        float inv = 1.0f / lsh[qr];
#pragma unroll
        for (int j = 0; j < 8; j++)
            g_ctx[(size_t)(q0 + qr) * H_ + h * DH_ + tx * 8 + j] = oacc[i][j] * inv;
    }
}

// ---------------- launch --------------------------------------------------
extern "C" void kernel_launch(void* const* d_in, const int* in_sizes, int n_in,
                              void* d_out, int out_size)
{
    const float* hidden      = (const float*)d_in[0];
    const float* am          = (const float*)d_in[1];
    const int*   pos         = (const int*)d_in[2];   // int32 (JAX downcasts int64)
    const float* Wqkv        = (const float*)d_in[3];
    const float* bqkv        = (const float*)d_in[4];
    const float* Wd          = (const float*)d_in[5];
    const float* bd          = (const float*)d_in[6];
    const float* scale_param = (const float*)d_in[7];
    const float* mem_keys    = (const float*)d_in[8];
    const float* mem_values  = (const float*)d_in[9];
    float*       out         = (float*)d_out;

    cudaFuncSetAttribute(knn_kernel, cudaFuncAttributeMaxDynamicSharedMemorySize, K3_SMEM);
    cudaFuncSetAttribute(attn_kernel, cudaFuncAttributeMaxDynamicSharedMemorySize, K4_SMEM);

    qkv_gemm_kernel<<<dim3(HQKV_ / 128, S_ / 128), 256>>>(hidden, Wqkv, bqkv);
    norm_rope_kernel<<<dim3(S_, NH_), 128>>>(pos);
    knn_kernel<<<dim3(S_ / 128, NH_), 256, K3_SMEM>>>(mem_keys);
    attn_kernel<<<dim3(S_ / 64, NH_), 256, K4_SMEM>>>(am, scale_param, mem_values);
    out_gemm_kernel<<<dim3(H_ / 128, S_ / 128), 256>>>(Wd, bd, out);
}